// round 5
// baseline (speedup 1.0000x reference)
#include <cuda_runtime.h>
#include <cstdint>

// ---------------------------------------------------------------------------
// ExpanderSimpleGraphSageLayer: scatter-mean over 1.6M edges + L2-normalize
//
// Inputs (metadata order):
//   d_in[0] h        float32 [N, D]        N=100000, D=128
//   d_in[1] b        float32 [N, D]
//   d_in[2] norm     float32 [N, 1]
//   d_in[3] edge_src int32   [E]           E=1600000
//   d_in[4] edge_dst int32   [E]
// Output: h_out [N,D] followed by b_out [N,2D]  (float32, N*3D elements)
// ---------------------------------------------------------------------------

#define NN 100000
#define DD 128

static __device__ float g_hn [NN * DD];   // h * norm   (pre-scaled messages)
static __device__ float g_acc[NN * DD];   // scatter-add accumulator
static __device__ float g_deg[NN];        // in-degree

// ---- phase 1: hn = h * norm -----------------------------------------------
__global__ void __launch_bounds__(256)
prescale_kernel(const float* __restrict__ h, const float* __restrict__ norm)
{
    int idx = blockIdx.x * blockDim.x + threadIdx.x;     // float4 index
    if (idx >= NN * (DD / 4)) return;
    int row = idx >> 5;                                  // 32 float4 per row
    float4 v = reinterpret_cast<const float4*>(h)[idx];
    float  s = __ldg(norm + row);
    v.x *= s; v.y *= s; v.z *= s; v.w *= s;
    reinterpret_cast<float4*>(g_hn)[idx] = v;
}

// ---- phase 2: edge scatter (one warp per edge) ----------------------------
__global__ void __launch_bounds__(256)
edge_kernel(const int* __restrict__ src, const int* __restrict__ dst, int E)
{
    int warp = (blockIdx.x * blockDim.x + threadIdx.x) >> 5;
    int lane = threadIdx.x & 31;
    if (warp >= E) return;

    int s = __ldg(src + warp);      // broadcast load (all lanes same addr)
    int t = __ldg(dst + warp);

    // gather one 512B row: lane -> float4
    float4 v = reinterpret_cast<const float4*>(g_hn)[s * 32 + lane];

    // vector reduction into accumulator (REDG, no return value)
    float* p = g_acc + (size_t)t * DD + lane * 4;
    asm volatile(
        "red.relaxed.gpu.global.add.v4.f32 [%0], {%1, %2, %3, %4};"
        :: "l"(p), "f"(v.x), "f"(v.y), "f"(v.z), "f"(v.w)
        : "memory");

    if (lane == 0)
        atomicAdd(g_deg + t, 1.0f);
}

// ---- phase 3: finalize per node (one warp per node) -----------------------
__global__ void __launch_bounds__(256)
finalize_kernel(const float* __restrict__ h, const float* __restrict__ b,
                const float* __restrict__ norm, float* __restrict__ out)
{
    int node = (blockIdx.x * blockDim.x + threadIdx.x) >> 5;
    int lane = threadIdx.x & 31;
    if (node >= NN) return;

    float inv_deg = 1.0f / fmaxf(g_deg[node], 1.0f);

    float4 c = reinterpret_cast<const float4*>(g_acc)[node * 32 + lane];
    c.x *= inv_deg; c.y *= inv_deg; c.z *= inv_deg; c.w *= inv_deg;

    float4 bv = reinterpret_cast<const float4*>(b)[node * 32 + lane];

    // sum of squares over concat(b, c): 256 values, 8 per lane
    float ss = bv.x * bv.x + bv.y * bv.y + bv.z * bv.z + bv.w * bv.w
             +  c.x *  c.x +  c.y *  c.y +  c.z *  c.z +  c.w *  c.w;
    #pragma unroll
    for (int m = 16; m; m >>= 1)
        ss += __shfl_xor_sync(0xffffffffu, ss, m);

    float inv_l2 = 1.0f / fmaxf(sqrtf(ss), 1e-12f);
    float nrm    = __ldg(norm + node);

    // h_out = h + c * norm
    float4 hv = reinterpret_cast<const float4*>(h)[node * 32 + lane];
    float4 ho;
    ho.x = hv.x + c.x * nrm;
    ho.y = hv.y + c.y * nrm;
    ho.z = hv.z + c.z * nrm;
    ho.w = hv.w + c.w * nrm;
    reinterpret_cast<float4*>(out)[node * 32 + lane] = ho;

    // b_out = concat(b, c) / l2
    float* bout = out + (size_t)NN * DD;
    float4 b1; b1.x = bv.x * inv_l2; b1.y = bv.y * inv_l2;
               b1.z = bv.z * inv_l2; b1.w = bv.w * inv_l2;
    float4 b2; b2.x =  c.x * inv_l2; b2.y =  c.y * inv_l2;
               b2.z =  c.z * inv_l2; b2.w =  c.w * inv_l2;
    reinterpret_cast<float4*>(bout)[node * 64 + lane]      = b1;
    reinterpret_cast<float4*>(bout)[node * 64 + 32 + lane] = b2;
}

// ---------------------------------------------------------------------------
extern "C" void kernel_launch(void* const* d_in, const int* in_sizes, int n_in,
                              void* d_out, int out_size)
{
    const float* h    = (const float*)d_in[0];
    const float* b    = (const float*)d_in[1];
    const float* norm = (const float*)d_in[2];
    const int*   esrc = (const int*)  d_in[3];
    const int*   edst = (const int*)  d_in[4];
    float*       out  = (float*)d_out;
    const int E = in_sizes[3];

    void* acc_ptr = nullptr;
    void* deg_ptr = nullptr;
    cudaGetSymbolAddress(&acc_ptr, g_acc);
    cudaGetSymbolAddress(&deg_ptr, g_deg);

    cudaMemsetAsync(acc_ptr, 0, (size_t)NN * DD * sizeof(float));
    cudaMemsetAsync(deg_ptr, 0, (size_t)NN * sizeof(float));

    {   // hn = h * norm
        int work = NN * (DD / 4);
        prescale_kernel<<<(work + 255) / 256, 256>>>(h, norm);
    }
    {   // edge scatter: one warp per edge
        long long threads = (long long)E * 32;
        int blocks = (int)((threads + 255) / 256);
        edge_kernel<<<blocks, 256>>>(esrc, edst, E);
    }
    {   // finalize: one warp per node
        long long threads = (long long)NN * 32;
        int blocks = (int)((threads + 255) / 256);
        finalize_kernel<<<blocks, 256>>>(h, b, norm, out);
    }
}

// round 6
// speedup vs baseline: 1.2812x; 1.2812x over previous
#include <cuda_runtime.h>
#include <cuda_fp16.h>

// ---------------------------------------------------------------------------
// ExpanderSimpleGraphSageLayer — CSR gather formulation, fp16 message staging
//
// Inputs (metadata order):
//   d_in[0] h        float32 [N, D]        N=100000, D=128
//   d_in[1] b        float32 [N, D]
//   d_in[2] norm     float32 [N, 1]
//   d_in[3] edge_src int32   [E]           E=1600000
//   d_in[4] edge_dst int32   [E]
// Output: h_out [N,D] followed by b_out [N,2D]  (float32, N*3D elements)
// ---------------------------------------------------------------------------

#define NN 100000
#define DD 128
#define EE 1600000

static __device__ __half g_hn16[NN * DD];    // fp16(h * norm)  (25.6 MB)
static __device__ int    g_count[NN];        // in-degree histogram
static __device__ int    g_cursor[NN];       // fill tickets
static __device__ int    g_rowstart[NN + 1]; // CSR row offsets
static __device__ int    g_csr[EE];          // src ids grouped by dst

// ---- phase 1: hn16 = fp16(h * norm) ---------------------------------------
__global__ void __launch_bounds__(256)
prescale16_kernel(const float* __restrict__ h, const float* __restrict__ norm)
{
    int idx = blockIdx.x * blockDim.x + threadIdx.x;   // one float4 (4 elems)
    if (idx >= NN * (DD / 4)) return;
    int row = idx >> 5;                                // 32 float4 per row
    float4 v = reinterpret_cast<const float4*>(h)[idx];
    float  s = __ldg(norm + row);
    __half2 lo = __floats2half2_rn(v.x * s, v.y * s);
    __half2 hi = __floats2half2_rn(v.z * s, v.w * s);
    uint2 u;
    u.x = *reinterpret_cast<unsigned*>(&lo);
    u.y = *reinterpret_cast<unsigned*>(&hi);
    reinterpret_cast<uint2*>(g_hn16)[idx] = u;
}

// ---- phase 2a: degree histogram -------------------------------------------
__global__ void __launch_bounds__(256)
hist_kernel(const int* __restrict__ dst, int E)
{
    int e = blockIdx.x * blockDim.x + threadIdx.x;
    if (e < E) atomicAdd(&g_count[__ldg(dst + e)], 1);
}

// ---- phase 2b: exclusive scan of 100k counts (single block) ---------------
__global__ void __launch_bounds__(1024)
scan_kernel()
{
    __shared__ int sh[1024];
    const int T = 1024;
    int tid   = threadIdx.x;
    int chunk = (NN + T - 1) / T;                      // 98
    int begin = tid * chunk;
    int end   = begin + chunk; if (end > NN) end = NN;
    if (begin > NN) begin = NN;

    int sum = 0;
    for (int i = begin; i < end; ++i) sum += g_count[i];
    sh[tid] = sum;
    __syncthreads();

    // inclusive Hillis–Steele scan
    for (int d = 1; d < T; d <<= 1) {
        int add = (tid >= d) ? sh[tid - d] : 0;
        __syncthreads();
        sh[tid] += add;
        __syncthreads();
    }
    int run = (tid == 0) ? 0 : sh[tid - 1];
    for (int i = begin; i < end; ++i) {
        g_rowstart[i] = run;
        run += g_count[i];
    }
    if (tid == T - 1) g_rowstart[NN] = run;            // == E
}

// ---- phase 2c: fill CSR ----------------------------------------------------
__global__ void __launch_bounds__(256)
fill_kernel(const int* __restrict__ src, const int* __restrict__ dst, int E)
{
    int e = blockIdx.x * blockDim.x + threadIdx.x;
    if (e >= E) return;
    int d   = __ldg(dst + e);
    int pos = g_rowstart[d] + atomicAdd(&g_cursor[d], 1);
    g_csr[pos] = __ldg(src + e);
}

// ---- phase 3: fused gather-mean + finalize (one warp per node) ------------
__global__ void __launch_bounds__(256)
gather_finalize_kernel(const float* __restrict__ h, const float* __restrict__ b,
                       const float* __restrict__ norm, float* __restrict__ out)
{
    int node = (blockIdx.x * blockDim.x + threadIdx.x) >> 5;
    int lane = threadIdx.x & 31;
    if (node >= NN) return;

    int start = g_rowstart[node];
    int end   = g_rowstart[node + 1];

    const uint2* hn = reinterpret_cast<const uint2*>(g_hn16);   // 32 uint2/row
    float4 acc = make_float4(0.f, 0.f, 0.f, 0.f);

    int e = start;
    for (; e + 1 < end; e += 2) {                   // 2-way MLP
        int s0 = __ldg(g_csr + e);
        int s1 = __ldg(g_csr + e + 1);
        uint2 r0 = hn[s0 * 32 + lane];
        uint2 r1 = hn[s1 * 32 + lane];
        float2 a0 = __half22float2(*reinterpret_cast<__half2*>(&r0.x));
        float2 a1 = __half22float2(*reinterpret_cast<__half2*>(&r0.y));
        float2 c0 = __half22float2(*reinterpret_cast<__half2*>(&r1.x));
        float2 c1 = __half22float2(*reinterpret_cast<__half2*>(&r1.y));
        acc.x += a0.x + c0.x;  acc.y += a0.y + c0.y;
        acc.z += a1.x + c1.x;  acc.w += a1.y + c1.y;
    }
    if (e < end) {
        int s0 = __ldg(g_csr + e);
        uint2 r0 = hn[s0 * 32 + lane];
        float2 a0 = __half22float2(*reinterpret_cast<__half2*>(&r0.x));
        float2 a1 = __half22float2(*reinterpret_cast<__half2*>(&r0.y));
        acc.x += a0.x;  acc.y += a0.y;
        acc.z += a1.x;  acc.w += a1.y;
    }

    float inv_deg = 1.0f / fmaxf((float)(end - start), 1.0f);
    float4 c;
    c.x = acc.x * inv_deg; c.y = acc.y * inv_deg;
    c.z = acc.z * inv_deg; c.w = acc.w * inv_deg;

    float4 bv = reinterpret_cast<const float4*>(b)[node * 32 + lane];

    // sum of squares over concat(b, c): 256 values, 8 per lane
    float ss = bv.x * bv.x + bv.y * bv.y + bv.z * bv.z + bv.w * bv.w
             +  c.x *  c.x +  c.y *  c.y +  c.z *  c.z +  c.w *  c.w;
    #pragma unroll
    for (int m = 16; m; m >>= 1)
        ss += __shfl_xor_sync(0xffffffffu, ss, m);

    float inv_l2 = 1.0f / fmaxf(sqrtf(ss), 1e-12f);
    float nrm    = __ldg(norm + node);

    // h_out = h + c * norm
    float4 hv = reinterpret_cast<const float4*>(h)[node * 32 + lane];
    float4 ho;
    ho.x = hv.x + c.x * nrm;
    ho.y = hv.y + c.y * nrm;
    ho.z = hv.z + c.z * nrm;
    ho.w = hv.w + c.w * nrm;
    reinterpret_cast<float4*>(out)[node * 32 + lane] = ho;

    // b_out = concat(b, c) / l2
    float* bout = out + (size_t)NN * DD;
    float4 b1; b1.x = bv.x * inv_l2; b1.y = bv.y * inv_l2;
               b1.z = bv.z * inv_l2; b1.w = bv.w * inv_l2;
    float4 b2; b2.x =  c.x * inv_l2; b2.y =  c.y * inv_l2;
               b2.z =  c.z * inv_l2; b2.w =  c.w * inv_l2;
    reinterpret_cast<float4*>(bout)[node * 64 + lane]      = b1;
    reinterpret_cast<float4*>(bout)[node * 64 + 32 + lane] = b2;
}

// ---------------------------------------------------------------------------
extern "C" void kernel_launch(void* const* d_in, const int* in_sizes, int n_in,
                              void* d_out, int out_size)
{
    const float* h    = (const float*)d_in[0];
    const float* b    = (const float*)d_in[1];
    const float* norm = (const float*)d_in[2];
    const int*   esrc = (const int*)  d_in[3];
    const int*   edst = (const int*)  d_in[4];
    float*       out  = (float*)d_out;
    int E = in_sizes[3];
    if (E > EE) E = EE;

    void* cnt_ptr = nullptr;
    void* cur_ptr = nullptr;
    cudaGetSymbolAddress(&cnt_ptr, g_count);
    cudaGetSymbolAddress(&cur_ptr, g_cursor);
    cudaMemsetAsync(cnt_ptr, 0, (size_t)NN * sizeof(int));
    cudaMemsetAsync(cur_ptr, 0, (size_t)NN * sizeof(int));

    {   // hn16 = fp16(h * norm)
        int work = NN * (DD / 4);
        prescale16_kernel<<<(work + 255) / 256, 256>>>(h, norm);
    }
    {   // CSR build
        int eb = (E + 255) / 256;
        hist_kernel<<<eb, 256>>>(edst, E);
        scan_kernel<<<1, 1024>>>();
        fill_kernel<<<eb, 256>>>(esrc, edst, E);
    }
    {   // fused gather-mean + finalize: one warp per node
        long long threads = (long long)NN * 32;
        int blocks = (int)((threads + 255) / 256);
        gather_finalize_kernel<<<blocks, 256>>>(h, b, norm, out);
    }
}

// round 7
// speedup vs baseline: 2.2567x; 1.7614x over previous
#include <cuda_runtime.h>
#include <cuda_fp16.h>

// ---------------------------------------------------------------------------
// ExpanderSimpleGraphSageLayer — CSR gather, fp16 staging, latency-optimized
//
// Inputs (metadata order):
//   d_in[0] h        float32 [N, D]        N=100000, D=128
//   d_in[1] b        float32 [N, D]
//   d_in[2] norm     float32 [N, 1]
//   d_in[3] edge_src int32   [E]           E=1600000
//   d_in[4] edge_dst int32   [E]
// Output: h_out [N,D] followed by b_out [N,2D]  (float32, N*3D elements)
// ---------------------------------------------------------------------------

#define NN 100000
#define DD 128
#define EE 1600000

#define SCAN_TPB 256
#define SCAN_IPT 4
#define SCAN_PER_BLK (SCAN_TPB * SCAN_IPT)                 // 1024
#define SCAN_NB ((NN + SCAN_PER_BLK - 1) / SCAN_PER_BLK)   // 98

static __device__ __half g_hn16[NN * DD];    // fp16(h * norm)  (25.6 MB)
static __device__ int    g_count[NN];        // in-degree histogram
static __device__ int    g_cursor[NN];       // atomic fill cursor (= rowstart copy)
static __device__ int    g_rowstart[NN + 1]; // CSR row offsets
static __device__ int    g_csr[EE];          // src ids grouped by dst
static __device__ int    g_bsum[SCAN_NB];    // per-block count sums
static __device__ int    g_boff[SCAN_NB];    // exclusive block offsets

// ---- phase 1: hn16 = fp16(h * norm) ---------------------------------------
__global__ void __launch_bounds__(256)
prescale16_kernel(const float* __restrict__ h, const float* __restrict__ norm)
{
    int idx = blockIdx.x * blockDim.x + threadIdx.x;   // one float4 (4 elems)
    if (idx >= NN * (DD / 4)) return;
    int row = idx >> 5;                                // 32 float4 per row
    float4 v = reinterpret_cast<const float4*>(h)[idx];
    float  s = __ldg(norm + row);
    __half2 lo = __floats2half2_rn(v.x * s, v.y * s);
    __half2 hi = __floats2half2_rn(v.z * s, v.w * s);
    uint2 u;
    u.x = *reinterpret_cast<unsigned*>(&lo);
    u.y = *reinterpret_cast<unsigned*>(&hi);
    reinterpret_cast<uint2*>(g_hn16)[idx] = u;
}

// ---- phase 2a: degree histogram (RED, no return — already throughput) ------
__global__ void __launch_bounds__(256)
hist_kernel(const int* __restrict__ dst, int E)
{
    int base = (blockIdx.x * blockDim.x + threadIdx.x) * 4;
    #pragma unroll
    for (int i = 0; i < 4; ++i) {
        int e = base + i;
        if (e < E) atomicAdd(&g_count[__ldg(dst + e)], 1);
    }
}

// ---- phase 2b-1: per-block sums of counts ----------------------------------
__global__ void __launch_bounds__(SCAN_TPB)
scan_sums_kernel()
{
    int base = blockIdx.x * SCAN_PER_BLK + threadIdx.x * SCAN_IPT;
    int s = 0;
    #pragma unroll
    for (int i = 0; i < SCAN_IPT; ++i) {
        int idx = base + i;
        if (idx < NN) s += g_count[idx];
    }
    // warp reduce
    #pragma unroll
    for (int m = 16; m; m >>= 1) s += __shfl_xor_sync(0xffffffffu, s, m);
    __shared__ int wsum[SCAN_TPB / 32];
    int lane = threadIdx.x & 31, wid = threadIdx.x >> 5;
    if (lane == 0) wsum[wid] = s;
    __syncthreads();
    if (threadIdx.x == 0) {
        int t = 0;
        #pragma unroll
        for (int j = 0; j < SCAN_TPB / 32; ++j) t += wsum[j];
        g_bsum[blockIdx.x] = t;
    }
}

// ---- phase 2b-2: exclusive scan of 98 block sums (tiny) --------------------
__global__ void __launch_bounds__(128)
scan_partials_kernel()
{
    __shared__ int sh[128];
    int tid = threadIdx.x;
    int v = (tid < SCAN_NB) ? g_bsum[tid] : 0;
    sh[tid] = v;
    __syncthreads();
    #pragma unroll
    for (int d = 1; d < 128; d <<= 1) {
        int add = (tid >= d) ? sh[tid - d] : 0;
        __syncthreads();
        sh[tid] += add;
        __syncthreads();
    }
    if (tid < SCAN_NB) g_boff[tid] = sh[tid] - v;
}

// ---- phase 2b-3: full exclusive scan -> rowstart + cursor ------------------
__global__ void __launch_bounds__(SCAN_TPB)
scan_apply_kernel(int E)
{
    int base = blockIdx.x * SCAN_PER_BLK + threadIdx.x * SCAN_IPT;
    int c[SCAN_IPT];
    #pragma unroll
    for (int i = 0; i < SCAN_IPT; ++i) {
        int idx = base + i;
        c[i] = (idx < NN) ? g_count[idx] : 0;
    }
    int t0 = c[0];
    int t1 = t0 + c[1];
    int t2 = t1 + c[2];
    int t3 = t2 + c[3];
    int tot = t3;

    int lane = threadIdx.x & 31, wid = threadIdx.x >> 5;
    int x = tot;
    #pragma unroll
    for (int d = 1; d < 32; d <<= 1) {
        int y = __shfl_up_sync(0xffffffffu, x, d);
        if (lane >= d) x += y;
    }
    int warp_excl = x - tot;

    __shared__ int wsum[SCAN_TPB / 32];
    __shared__ int woff[SCAN_TPB / 32];
    if (lane == 31) wsum[wid] = x;
    __syncthreads();
    if (threadIdx.x == 0) {
        int r = 0;
        #pragma unroll
        for (int j = 0; j < SCAN_TPB / 32; ++j) { woff[j] = r; r += wsum[j]; }
    }
    __syncthreads();

    int off = g_boff[blockIdx.x] + woff[wid] + warp_excl;
    int ex[SCAN_IPT] = { off, off + t0, off + t1, off + t2 };
    #pragma unroll
    for (int i = 0; i < SCAN_IPT; ++i) {
        int idx = base + i;
        if (idx < NN) {
            g_rowstart[idx] = ex[i];
            g_cursor[idx]   = ex[i];
        }
    }
    if (blockIdx.x == 0 && threadIdx.x == 0) g_rowstart[NN] = E;
}

// ---- phase 2c: fill CSR (4 independent atomic chains per thread) ----------
__global__ void __launch_bounds__(256)
fill_kernel(const int* __restrict__ src, const int* __restrict__ dst, int E)
{
    int base = (blockIdx.x * blockDim.x + threadIdx.x) * 4;
    int d[4], s[4], p[4];
    bool ok[4];
    #pragma unroll
    for (int i = 0; i < 4; ++i) {
        int e = base + i;
        ok[i] = e < E;
        d[i] = ok[i] ? __ldg(dst + e) : 0;
        s[i] = ok[i] ? __ldg(src + e) : 0;
    }
    #pragma unroll
    for (int i = 0; i < 4; ++i)
        if (ok[i]) p[i] = atomicAdd(&g_cursor[d[i]], 1);
    #pragma unroll
    for (int i = 0; i < 4; ++i)
        if (ok[i]) g_csr[p[i]] = s[i];
}

// ---- phase 3: fused gather-mean + finalize (one warp per node, MLP=4) -----
__global__ void __launch_bounds__(256)
gather_finalize_kernel(const float* __restrict__ h, const float* __restrict__ b,
                       const float* __restrict__ norm, float* __restrict__ out)
{
    int node = (blockIdx.x * blockDim.x + threadIdx.x) >> 5;
    int lane = threadIdx.x & 31;
    if (node >= NN) return;

    int start = __ldg(g_rowstart + node);
    int end   = __ldg(g_rowstart + node + 1);

    const uint2* hn = reinterpret_cast<const uint2*>(g_hn16);   // 32 uint2/row
    float4 acc = make_float4(0.f, 0.f, 0.f, 0.f);

    int e = start;
    for (; e + 3 < end; e += 4) {                   // 4 rows in flight
        int s0 = __ldg(g_csr + e);
        int s1 = __ldg(g_csr + e + 1);
        int s2 = __ldg(g_csr + e + 2);
        int s3 = __ldg(g_csr + e + 3);
        uint2 r0 = hn[s0 * 32 + lane];
        uint2 r1 = hn[s1 * 32 + lane];
        uint2 r2 = hn[s2 * 32 + lane];
        uint2 r3 = hn[s3 * 32 + lane];
        #pragma unroll
        for (int k = 0; k < 1; ++k) {}              // (keep loads batched)
        float2 a0 = __half22float2(*reinterpret_cast<__half2*>(&r0.x));
        float2 a1 = __half22float2(*reinterpret_cast<__half2*>(&r0.y));
        float2 b0 = __half22float2(*reinterpret_cast<__half2*>(&r1.x));
        float2 b1 = __half22float2(*reinterpret_cast<__half2*>(&r1.y));
        float2 c0 = __half22float2(*reinterpret_cast<__half2*>(&r2.x));
        float2 c1 = __half22float2(*reinterpret_cast<__half2*>(&r2.y));
        float2 d0 = __half22float2(*reinterpret_cast<__half2*>(&r3.x));
        float2 d1 = __half22float2(*reinterpret_cast<__half2*>(&r3.y));
        acc.x += (a0.x + b0.x) + (c0.x + d0.x);
        acc.y += (a0.y + b0.y) + (c0.y + d0.y);
        acc.z += (a1.x + b1.x) + (c1.x + d1.x);
        acc.w += (a1.y + b1.y) + (c1.y + d1.y);
    }
    for (; e < end; ++e) {
        int s0 = __ldg(g_csr + e);
        uint2 r0 = hn[s0 * 32 + lane];
        float2 a0 = __half22float2(*reinterpret_cast<__half2*>(&r0.x));
        float2 a1 = __half22float2(*reinterpret_cast<__half2*>(&r0.y));
        acc.x += a0.x;  acc.y += a0.y;
        acc.z += a1.x;  acc.w += a1.y;
    }

    float inv_deg = 1.0f / fmaxf((float)(end - start), 1.0f);
    float4 c;
    c.x = acc.x * inv_deg; c.y = acc.y * inv_deg;
    c.z = acc.z * inv_deg; c.w = acc.w * inv_deg;

    float4 bv = reinterpret_cast<const float4*>(b)[node * 32 + lane];

    // sum of squares over concat(b, c): 256 values, 8 per lane
    float ss = bv.x * bv.x + bv.y * bv.y + bv.z * bv.z + bv.w * bv.w
             +  c.x *  c.x +  c.y *  c.y +  c.z *  c.z +  c.w *  c.w;
    #pragma unroll
    for (int m = 16; m; m >>= 1)
        ss += __shfl_xor_sync(0xffffffffu, ss, m);

    float inv_l2 = 1.0f / fmaxf(sqrtf(ss), 1e-12f);
    float nrm    = __ldg(norm + node);

    // h_out = h + c * norm
    float4 hv = reinterpret_cast<const float4*>(h)[node * 32 + lane];
    float4 ho;
    ho.x = hv.x + c.x * nrm;
    ho.y = hv.y + c.y * nrm;
    ho.z = hv.z + c.z * nrm;
    ho.w = hv.w + c.w * nrm;
    reinterpret_cast<float4*>(out)[node * 32 + lane] = ho;

    // b_out = concat(b, c) / l2
    float* bout = out + (size_t)NN * DD;
    float4 b1; b1.x = bv.x * inv_l2; b1.y = bv.y * inv_l2;
               b1.z = bv.z * inv_l2; b1.w = bv.w * inv_l2;
    float4 b2; b2.x =  c.x * inv_l2; b2.y =  c.y * inv_l2;
               b2.z =  c.z * inv_l2; b2.w =  c.w * inv_l2;
    reinterpret_cast<float4*>(bout)[node * 64 + lane]      = b1;
    reinterpret_cast<float4*>(bout)[node * 64 + 32 + lane] = b2;
}

// ---------------------------------------------------------------------------
extern "C" void kernel_launch(void* const* d_in, const int* in_sizes, int n_in,
                              void* d_out, int out_size)
{
    const float* h    = (const float*)d_in[0];
    const float* b    = (const float*)d_in[1];
    const float* norm = (const float*)d_in[2];
    const int*   esrc = (const int*)  d_in[3];
    const int*   edst = (const int*)  d_in[4];
    float*       out  = (float*)d_out;
    int E = in_sizes[3];
    if (E > EE) E = EE;

    void* cnt_ptr = nullptr;
    cudaGetSymbolAddress(&cnt_ptr, g_count);
    cudaMemsetAsync(cnt_ptr, 0, (size_t)NN * sizeof(int));

    {   // hn16 = fp16(h * norm)
        int work = NN * (DD / 4);
        prescale16_kernel<<<(work + 255) / 256, 256>>>(h, norm);
    }
    {   // CSR build
        int eb4 = (E / 4 + 255) / 256 + 1;
        hist_kernel<<<eb4, 256>>>(edst, E);
        scan_sums_kernel<<<SCAN_NB, SCAN_TPB>>>();
        scan_partials_kernel<<<1, 128>>>();
        scan_apply_kernel<<<SCAN_NB, SCAN_TPB>>>(E);
        fill_kernel<<<eb4, 256>>>(esrc, edst, E);
    }
    {   // fused gather-mean + finalize: one warp per node
        long long threads = (long long)NN * 32;
        int blocks = (int)((threads + 255) / 256);
        gather_finalize_kernel<<<blocks, 256>>>(h, b, norm, out);
    }
}

// round 8
// speedup vs baseline: 2.3391x; 1.0365x over previous
#include <cuda_runtime.h>
#include <cuda_fp16.h>

// ---------------------------------------------------------------------------
// ExpanderSimpleGraphSageLayer — CSR gather, fp16 staging
// R8: fused prescale∥hist, single-pass decoupled-lookback scan, 5 graph nodes
//
// Inputs (metadata order):
//   d_in[0] h        float32 [N, D]        N=100000, D=128
//   d_in[1] b        float32 [N, D]
//   d_in[2] norm     float32 [N, 1]
//   d_in[3] edge_src int32   [E]           E=1600000
//   d_in[4] edge_dst int32   [E]
// Output: h_out [N,D] followed by b_out [N,2D]  (float32, N*3D elements)
// ---------------------------------------------------------------------------

#define NN 100000
#define DD 128
#define EE 1600000

#define SCAN_TPB 256
#define SCAN_IPT 4
#define SCAN_PER_BLK (SCAN_TPB * SCAN_IPT)                 // 1024
#define SCAN_NB ((NN + SCAN_PER_BLK - 1) / SCAN_PER_BLK)   // 98  (< 148 SMs)

static __device__ __half g_hn16[NN * DD];    // fp16(h * norm)  (25.6 MB)
static __device__ int    g_cursor[NN];       // atomic fill cursor
static __device__ int    g_rowstart[NN + 1]; // CSR row offsets
static __device__ int    g_csr[EE];          // src ids grouped by dst

// zero-region: [count (NN int)] [scan state (SCAN_NB u64)] — one memset
static __device__ __align__(16) unsigned char g_zero[NN * 4 + SCAN_NB * 8];
#define G_COUNT ((int*)g_zero)
#define G_STATE ((unsigned long long*)(g_zero + NN * 4))
// state word: (status << 32) | value.  status: 0=empty, 1=aggregate, 2=inclusive

// ---- phase 1: fused  prescale (blocks [0,preB))  ∥  hist (rest) -----------
__global__ void __launch_bounds__(256)
fused_pre_hist_kernel(const float* __restrict__ h, const float* __restrict__ norm,
                      const int* __restrict__ dst, int E, int preB)
{
    if ((int)blockIdx.x < preB) {
        int idx = blockIdx.x * 256 + threadIdx.x;          // one float4
        if (idx >= NN * (DD / 4)) return;
        int row = idx >> 5;                                // 32 float4 per row
        float4 v = reinterpret_cast<const float4*>(h)[idx];
        float  s = __ldg(norm + row);
        __half2 lo = __floats2half2_rn(v.x * s, v.y * s);
        __half2 hi = __floats2half2_rn(v.z * s, v.w * s);
        uint2 u;
        u.x = *reinterpret_cast<unsigned*>(&lo);
        u.y = *reinterpret_cast<unsigned*>(&hi);
        reinterpret_cast<uint2*>(g_hn16)[idx] = u;
    } else {
        int base = ((blockIdx.x - preB) * 256 + threadIdx.x) * 4;
        #pragma unroll
        for (int i = 0; i < 4; ++i) {
            int e = base + i;
            if (e < E) atomicAdd(&G_COUNT[__ldg(dst + e)], 1);
        }
    }
}

// ---- phase 2: single-pass exclusive scan (decoupled lookback) --------------
__global__ void __launch_bounds__(SCAN_TPB)
scan_onepass_kernel(int E)
{
    int blk  = blockIdx.x;
    int lane = threadIdx.x & 31, wid = threadIdx.x >> 5;
    int base = blk * SCAN_PER_BLK + threadIdx.x * SCAN_IPT;

    int c[SCAN_IPT];
    #pragma unroll
    for (int i = 0; i < SCAN_IPT; ++i) {
        int idx = base + i;
        c[i] = (idx < NN) ? G_COUNT[idx] : 0;
    }
    int t0 = c[0];
    int t1 = t0 + c[1];
    int t2 = t1 + c[2];
    int t3 = t2 + c[3];
    int tot = t3;

    // warp inclusive scan of per-thread totals
    int x = tot;
    #pragma unroll
    for (int d = 1; d < 32; d <<= 1) {
        int y = __shfl_up_sync(0xffffffffu, x, d);
        if (lane >= d) x += y;
    }
    int warp_excl = x - tot;

    __shared__ int wsum[SCAN_TPB / 32];
    __shared__ int woff[SCAN_TPB / 32];
    __shared__ int sh_btotal;
    __shared__ unsigned sh_excl;
    if (lane == 31) wsum[wid] = x;
    __syncthreads();
    if (threadIdx.x == 0) {
        int r = 0;
        #pragma unroll
        for (int j = 0; j < SCAN_TPB / 32; ++j) { woff[j] = r; r += wsum[j]; }
        sh_btotal = r;
        sh_excl = 0;
    }
    __syncthreads();
    int btotal = sh_btotal;

    // publish aggregate / inclusive, then lookback (warp 0)
    if (blk == 0) {
        if (threadIdx.x == 0) {
            __threadfence();
            *(volatile unsigned long long*)&G_STATE[0] =
                (2ull << 32) | (unsigned)btotal;
        }
    } else if (wid == 0) {
        if (lane == 0) {
            __threadfence();
            *(volatile unsigned long long*)&G_STATE[blk] =
                (1ull << 32) | (unsigned)btotal;
        }
        unsigned running = 0;
        int idx = blk - 1;
        for (;;) {
            int j = idx - lane;
            bool valid = j >= 0;
            unsigned long long st;
            for (;;) {
                st = valid ? *(volatile const unsigned long long*)&G_STATE[j]
                           : (2ull << 32);
                if (!__any_sync(0xffffffffu, (unsigned)(st >> 32) == 0u)) break;
            }
            unsigned stat = (unsigned)(st >> 32);
            unsigned val  = (unsigned)st;
            unsigned mask2 = __ballot_sync(0xffffffffu, stat == 2u);
            if (mask2) {
                int firstIncl = __ffs(mask2) - 1;   // closest inclusive
                unsigned contrib = (lane <= firstIncl) ? val : 0u;
                #pragma unroll
                for (int m = 16; m; m >>= 1)
                    contrib += __shfl_xor_sync(0xffffffffu, contrib, m);
                running += contrib;
                break;
            } else {
                unsigned contrib = val;
                #pragma unroll
                for (int m = 16; m; m >>= 1)
                    contrib += __shfl_xor_sync(0xffffffffu, contrib, m);
                running += contrib;
                idx -= 32;
            }
        }
        if (lane == 0) {
            sh_excl = running;
            __threadfence();
            *(volatile unsigned long long*)&G_STATE[blk] =
                (2ull << 32) | (unsigned)(running + btotal);
        }
    }
    __syncthreads();
    unsigned excl = sh_excl;

    int off = (int)excl + woff[wid] + warp_excl;
    int ex[SCAN_IPT] = { off, off + t0, off + t1, off + t2 };
    #pragma unroll
    for (int i = 0; i < SCAN_IPT; ++i) {
        int idx = base + i;
        if (idx < NN) {
            g_rowstart[idx] = ex[i];
            g_cursor[idx]   = ex[i];
        }
    }
    if (blk == 0 && threadIdx.x == 0) g_rowstart[NN] = E;
}

// ---- phase 3: fill CSR (4 independent atomic chains per thread) ------------
__global__ void __launch_bounds__(256)
fill_kernel(const int* __restrict__ src, const int* __restrict__ dst, int E)
{
    int base = (blockIdx.x * blockDim.x + threadIdx.x) * 4;
    int d[4], s[4], p[4];
    bool ok[4];
    #pragma unroll
    for (int i = 0; i < 4; ++i) {
        int e = base + i;
        ok[i] = e < E;
        d[i] = ok[i] ? __ldg(dst + e) : 0;
        s[i] = ok[i] ? __ldg(src + e) : 0;
    }
    #pragma unroll
    for (int i = 0; i < 4; ++i)
        if (ok[i]) p[i] = atomicAdd(&g_cursor[d[i]], 1);
    #pragma unroll
    for (int i = 0; i < 4; ++i)
        if (ok[i]) g_csr[p[i]] = s[i];
}

// ---- phase 4: fused gather-mean + finalize (one warp per node, MLP=8) ------
__global__ void __launch_bounds__(256)
gather_finalize_kernel(const float* __restrict__ h, const float* __restrict__ b,
                       const float* __restrict__ norm, float* __restrict__ out)
{
    int node = (blockIdx.x * blockDim.x + threadIdx.x) >> 5;
    int lane = threadIdx.x & 31;
    if (node >= NN) return;

    int start = __ldg(g_rowstart + node);
    int end   = __ldg(g_rowstart + node + 1);

    const uint2* hn = reinterpret_cast<const uint2*>(g_hn16);   // 32 uint2/row
    float4 acc = make_float4(0.f, 0.f, 0.f, 0.f);

    int e = start;
    for (; e + 7 < end; e += 8) {                   // 8 rows in flight
        int s[8];
        #pragma unroll
        for (int i = 0; i < 8; ++i) s[i] = __ldg(g_csr + e + i);
        uint2 r[8];
        #pragma unroll
        for (int i = 0; i < 8; ++i) r[i] = hn[s[i] * 32 + lane];
        #pragma unroll
        for (int i = 0; i < 8; ++i) {
            float2 a0 = __half22float2(*reinterpret_cast<__half2*>(&r[i].x));
            float2 a1 = __half22float2(*reinterpret_cast<__half2*>(&r[i].y));
            acc.x += a0.x;  acc.y += a0.y;
            acc.z += a1.x;  acc.w += a1.y;
        }
    }
    for (; e < end; ++e) {
        int s0 = __ldg(g_csr + e);
        uint2 r0 = hn[s0 * 32 + lane];
        float2 a0 = __half22float2(*reinterpret_cast<__half2*>(&r0.x));
        float2 a1 = __half22float2(*reinterpret_cast<__half2*>(&r0.y));
        acc.x += a0.x;  acc.y += a0.y;
        acc.z += a1.x;  acc.w += a1.y;
    }

    float inv_deg = 1.0f / fmaxf((float)(end - start), 1.0f);
    float4 c;
    c.x = acc.x * inv_deg; c.y = acc.y * inv_deg;
    c.z = acc.z * inv_deg; c.w = acc.w * inv_deg;

    float4 bv = reinterpret_cast<const float4*>(b)[node * 32 + lane];

    // sum of squares over concat(b, c): 256 values, 8 per lane
    float ss = bv.x * bv.x + bv.y * bv.y + bv.z * bv.z + bv.w * bv.w
             +  c.x *  c.x +  c.y *  c.y +  c.z *  c.z +  c.w *  c.w;
    #pragma unroll
    for (int m = 16; m; m >>= 1)
        ss += __shfl_xor_sync(0xffffffffu, ss, m);

    float inv_l2 = 1.0f / fmaxf(sqrtf(ss), 1e-12f);
    float nrm    = __ldg(norm + node);

    // h_out = h + c * norm
    float4 hv = reinterpret_cast<const float4*>(h)[node * 32 + lane];
    float4 ho;
    ho.x = hv.x + c.x * nrm;
    ho.y = hv.y + c.y * nrm;
    ho.z = hv.z + c.z * nrm;
    ho.w = hv.w + c.w * nrm;
    reinterpret_cast<float4*>(out)[node * 32 + lane] = ho;

    // b_out = concat(b, c) / l2
    float* bout = out + (size_t)NN * DD;
    float4 b1; b1.x = bv.x * inv_l2; b1.y = bv.y * inv_l2;
               b1.z = bv.z * inv_l2; b1.w = bv.w * inv_l2;
    float4 b2; b2.x =  c.x * inv_l2; b2.y =  c.y * inv_l2;
               b2.z =  c.z * inv_l2; b2.w =  c.w * inv_l2;
    reinterpret_cast<float4*>(bout)[node * 64 + lane]      = b1;
    reinterpret_cast<float4*>(bout)[node * 64 + 32 + lane] = b2;
}

// ---------------------------------------------------------------------------
extern "C" void kernel_launch(void* const* d_in, const int* in_sizes, int n_in,
                              void* d_out, int out_size)
{
    const float* h    = (const float*)d_in[0];
    const float* b    = (const float*)d_in[1];
    const float* norm = (const float*)d_in[2];
    const int*   esrc = (const int*)  d_in[3];
    const int*   edst = (const int*)  d_in[4];
    float*       out  = (float*)d_out;
    int E = in_sizes[3];
    if (E > EE) E = EE;

    void* zero_ptr = nullptr;
    cudaGetSymbolAddress(&zero_ptr, g_zero);
    cudaMemsetAsync(zero_ptr, 0, (size_t)NN * 4 + SCAN_NB * 8);

    // fused prescale ∥ hist
    int preB  = (NN * (DD / 4) + 255) / 256;            // 12500
    int histB = (E + 1023) / 1024;                      // 1563
    fused_pre_hist_kernel<<<preB + histB, 256>>>(h, norm, edst, E, preB);

    // single-pass scan -> rowstart + cursor
    scan_onepass_kernel<<<SCAN_NB, SCAN_TPB>>>(E);

    // CSR fill
    int eb4 = (E / 4 + 255) / 256 + 1;
    fill_kernel<<<eb4, 256>>>(esrc, edst, E);

    // fused gather-mean + finalize: one warp per node
    long long threads = (long long)NN * 32;
    int blocks = (int)((threads + 255) / 256);
    gather_finalize_kernel<<<blocks, 256>>>(h, b, norm, out);
}

// round 9
// speedup vs baseline: 2.4654x; 1.0540x over previous
#include <cuda_runtime.h>
#include <cuda_fp16.h>

// ---------------------------------------------------------------------------
// ExpanderSimpleGraphSageLayer — CSR gather, fp16 staging
// R9: streaming cache hints protect hn16 L2 residency; MLP tail tiers; fill x8
//
// Inputs (metadata order):
//   d_in[0] h        float32 [N, D]        N=100000, D=128
//   d_in[1] b        float32 [N, D]
//   d_in[2] norm     float32 [N, 1]
//   d_in[3] edge_src int32   [E]           E=1600000
//   d_in[4] edge_dst int32   [E]
// Output: h_out [N,D] followed by b_out [N,2D]  (float32, N*3D elements)
// ---------------------------------------------------------------------------

#define NN 100000
#define DD 128
#define EE 1600000

#define SCAN_TPB 256
#define SCAN_IPT 4
#define SCAN_PER_BLK (SCAN_TPB * SCAN_IPT)                 // 1024
#define SCAN_NB ((NN + SCAN_PER_BLK - 1) / SCAN_PER_BLK)   // 98  (< 148 SMs)

static __device__ __half g_hn16[NN * DD];    // fp16(h * norm)  (25.6 MB)
static __device__ int    g_cursor[NN];       // atomic fill cursor
static __device__ int    g_rowstart[NN + 1]; // CSR row offsets
static __device__ int    g_csr[EE];          // src ids grouped by dst

// zero-region: [count (NN int)] [scan state (SCAN_NB u64)] — one memset
static __device__ __align__(16) unsigned char g_zero[NN * 4 + SCAN_NB * 8];
#define G_COUNT ((int*)g_zero)
#define G_STATE ((unsigned long long*)(g_zero + NN * 4))
// state word: (status << 32) | value.  status: 0=empty, 1=aggregate, 2=inclusive

// ---- streaming load/store helpers -----------------------------------------
__device__ __forceinline__ float4 ldcs4(const float4* p) {
    float4 v;
    asm volatile("ld.global.cs.v4.f32 {%0,%1,%2,%3}, [%4];"
                 : "=f"(v.x), "=f"(v.y), "=f"(v.z), "=f"(v.w) : "l"(p));
    return v;
}
__device__ __forceinline__ void stcs4(float4* p, float4 v) {
    asm volatile("st.global.cs.v4.f32 [%0], {%1,%2,%3,%4};"
                 :: "l"(p), "f"(v.x), "f"(v.y), "f"(v.z), "f"(v.w) : "memory");
}

// ---- phase 1: fused  prescale (blocks [0,preB))  ∥  hist (rest) -----------
__global__ void __launch_bounds__(256)
fused_pre_hist_kernel(const float* __restrict__ h, const float* __restrict__ norm,
                      const int* __restrict__ dst, int E, int preB)
{
    if ((int)blockIdx.x < preB) {
        int idx = blockIdx.x * 256 + threadIdx.x;          // one float4
        if (idx >= NN * (DD / 4)) return;
        int row = idx >> 5;                                // 32 float4 per row
        float4 v = ldcs4(reinterpret_cast<const float4*>(h) + idx);
        float  s = __ldg(norm + row);
        __half2 lo = __floats2half2_rn(v.x * s, v.y * s);
        __half2 hi = __floats2half2_rn(v.z * s, v.w * s);
        uint2 u;
        u.x = *reinterpret_cast<unsigned*>(&lo);
        u.y = *reinterpret_cast<unsigned*>(&hi);
        reinterpret_cast<uint2*>(g_hn16)[idx] = u;
    } else {
        int base = ((blockIdx.x - preB) * 256 + threadIdx.x) * 4;
        #pragma unroll
        for (int i = 0; i < 4; ++i) {
            int e = base + i;
            if (e < E) atomicAdd(&G_COUNT[__ldg(dst + e)], 1);
        }
    }
}

// ---- phase 2: single-pass exclusive scan (decoupled lookback) --------------
__global__ void __launch_bounds__(SCAN_TPB)
scan_onepass_kernel(int E)
{
    int blk  = blockIdx.x;
    int lane = threadIdx.x & 31, wid = threadIdx.x >> 5;
    int base = blk * SCAN_PER_BLK + threadIdx.x * SCAN_IPT;

    int c[SCAN_IPT];
    #pragma unroll
    for (int i = 0; i < SCAN_IPT; ++i) {
        int idx = base + i;
        c[i] = (idx < NN) ? G_COUNT[idx] : 0;
    }
    int t0 = c[0];
    int t1 = t0 + c[1];
    int t2 = t1 + c[2];
    int t3 = t2 + c[3];
    int tot = t3;

    // warp inclusive scan of per-thread totals
    int x = tot;
    #pragma unroll
    for (int d = 1; d < 32; d <<= 1) {
        int y = __shfl_up_sync(0xffffffffu, x, d);
        if (lane >= d) x += y;
    }
    int warp_excl = x - tot;

    __shared__ int wsum[SCAN_TPB / 32];
    __shared__ int woff[SCAN_TPB / 32];
    __shared__ int sh_btotal;
    __shared__ unsigned sh_excl;
    if (lane == 31) wsum[wid] = x;
    __syncthreads();
    if (threadIdx.x == 0) {
        int r = 0;
        #pragma unroll
        for (int j = 0; j < SCAN_TPB / 32; ++j) { woff[j] = r; r += wsum[j]; }
        sh_btotal = r;
        sh_excl = 0;
    }
    __syncthreads();
    int btotal = sh_btotal;

    if (blk == 0) {
        if (threadIdx.x == 0) {
            __threadfence();
            *(volatile unsigned long long*)&G_STATE[0] =
                (2ull << 32) | (unsigned)btotal;
        }
    } else if (wid == 0) {
        if (lane == 0) {
            __threadfence();
            *(volatile unsigned long long*)&G_STATE[blk] =
                (1ull << 32) | (unsigned)btotal;
        }
        unsigned running = 0;
        int idx = blk - 1;
        for (;;) {
            int j = idx - lane;
            bool valid = j >= 0;
            unsigned long long st;
            for (;;) {
                st = valid ? *(volatile const unsigned long long*)&G_STATE[j]
                           : (2ull << 32);
                if (!__any_sync(0xffffffffu, (unsigned)(st >> 32) == 0u)) break;
            }
            unsigned stat = (unsigned)(st >> 32);
            unsigned val  = (unsigned)st;
            unsigned mask2 = __ballot_sync(0xffffffffu, stat == 2u);
            if (mask2) {
                int firstIncl = __ffs(mask2) - 1;   // closest inclusive
                unsigned contrib = (lane <= firstIncl) ? val : 0u;
                #pragma unroll
                for (int m = 16; m; m >>= 1)
                    contrib += __shfl_xor_sync(0xffffffffu, contrib, m);
                running += contrib;
                break;
            } else {
                unsigned contrib = val;
                #pragma unroll
                for (int m = 16; m; m >>= 1)
                    contrib += __shfl_xor_sync(0xffffffffu, contrib, m);
                running += contrib;
                idx -= 32;
            }
        }
        if (lane == 0) {
            sh_excl = running;
            __threadfence();
            *(volatile unsigned long long*)&G_STATE[blk] =
                (2ull << 32) | (unsigned)(running + btotal);
        }
    }
    __syncthreads();
    unsigned excl = sh_excl;

    int off = (int)excl + woff[wid] + warp_excl;
    int ex[SCAN_IPT] = { off, off + t0, off + t1, off + t2 };
    #pragma unroll
    for (int i = 0; i < SCAN_IPT; ++i) {
        int idx = base + i;
        if (idx < NN) {
            g_rowstart[idx] = ex[i];
            g_cursor[idx]   = ex[i];
        }
    }
    if (blk == 0 && threadIdx.x == 0) g_rowstart[NN] = E;
}

// ---- phase 3: fill CSR (8 independent atomic chains per thread) ------------
__global__ void __launch_bounds__(256)
fill_kernel(const int* __restrict__ src, const int* __restrict__ dst, int E)
{
    int base = (blockIdx.x * blockDim.x + threadIdx.x) * 8;
    int d[8], s[8], p[8];
    bool ok[8];
    #pragma unroll
    for (int i = 0; i < 8; ++i) {
        int e = base + i;
        ok[i] = e < E;
        d[i] = ok[i] ? __ldg(dst + e) : 0;
        s[i] = ok[i] ? __ldg(src + e) : 0;
    }
    #pragma unroll
    for (int i = 0; i < 8; ++i)
        if (ok[i]) p[i] = atomicAdd(&g_cursor[d[i]], 1);
    #pragma unroll
    for (int i = 0; i < 8; ++i)
        if (ok[i]) g_csr[p[i]] = s[i];
}

// ---- phase 4: fused gather-mean + finalize (one warp per node) -------------
__global__ void __launch_bounds__(256)
gather_finalize_kernel(const float* __restrict__ h, const float* __restrict__ b,
                       const float* __restrict__ norm, float* __restrict__ out)
{
    int node = (blockIdx.x * blockDim.x + threadIdx.x) >> 5;
    int lane = threadIdx.x & 31;
    if (node >= NN) return;

    int start = __ldg(g_rowstart + node);
    int end   = __ldg(g_rowstart + node + 1);

    const uint2* hn = reinterpret_cast<const uint2*>(g_hn16);   // 32 uint2/row
    float4 acc = make_float4(0.f, 0.f, 0.f, 0.f);

    int e = start;
    for (; e + 7 < end; e += 8) {                   // 8 rows in flight
        int s[8];
        #pragma unroll
        for (int i = 0; i < 8; ++i) s[i] = __ldg(g_csr + e + i);
        uint2 r[8];
        #pragma unroll
        for (int i = 0; i < 8; ++i) r[i] = hn[s[i] * 32 + lane];
        #pragma unroll
        for (int i = 0; i < 8; ++i) {
            float2 a0 = __half22float2(*reinterpret_cast<__half2*>(&r[i].x));
            float2 a1 = __half22float2(*reinterpret_cast<__half2*>(&r[i].y));
            acc.x += a0.x;  acc.y += a0.y;
            acc.z += a1.x;  acc.w += a1.y;
        }
    }
    if (e + 3 < end) {                              // 4-wide tail
        int s[4];
        #pragma unroll
        for (int i = 0; i < 4; ++i) s[i] = __ldg(g_csr + e + i);
        uint2 r[4];
        #pragma unroll
        for (int i = 0; i < 4; ++i) r[i] = hn[s[i] * 32 + lane];
        #pragma unroll
        for (int i = 0; i < 4; ++i) {
            float2 a0 = __half22float2(*reinterpret_cast<__half2*>(&r[i].x));
            float2 a1 = __half22float2(*reinterpret_cast<__half2*>(&r[i].y));
            acc.x += a0.x;  acc.y += a0.y;
            acc.z += a1.x;  acc.w += a1.y;
        }
        e += 4;
    }
    if (e + 1 < end) {                              // 2-wide tail
        int s0 = __ldg(g_csr + e);
        int s1 = __ldg(g_csr + e + 1);
        uint2 r0 = hn[s0 * 32 + lane];
        uint2 r1 = hn[s1 * 32 + lane];
        float2 a0 = __half22float2(*reinterpret_cast<__half2*>(&r0.x));
        float2 a1 = __half22float2(*reinterpret_cast<__half2*>(&r0.y));
        float2 c0 = __half22float2(*reinterpret_cast<__half2*>(&r1.x));
        float2 c1 = __half22float2(*reinterpret_cast<__half2*>(&r1.y));
        acc.x += a0.x + c0.x;  acc.y += a0.y + c0.y;
        acc.z += a1.x + c1.x;  acc.w += a1.y + c1.y;
        e += 2;
    }
    if (e < end) {
        int s0 = __ldg(g_csr + e);
        uint2 r0 = hn[s0 * 32 + lane];
        float2 a0 = __half22float2(*reinterpret_cast<__half2*>(&r0.x));
        float2 a1 = __half22float2(*reinterpret_cast<__half2*>(&r0.y));
        acc.x += a0.x;  acc.y += a0.y;
        acc.z += a1.x;  acc.w += a1.y;
    }

    float inv_deg = 1.0f / fmaxf((float)(end - start), 1.0f);
    float4 c;
    c.x = acc.x * inv_deg; c.y = acc.y * inv_deg;
    c.z = acc.z * inv_deg; c.w = acc.w * inv_deg;

    // streaming reads: evict-first so hn16/csr stay L2-resident
    float4 bv = ldcs4(reinterpret_cast<const float4*>(b) + node * 32 + lane);

    // sum of squares over concat(b, c): 256 values, 8 per lane
    float ss = bv.x * bv.x + bv.y * bv.y + bv.z * bv.z + bv.w * bv.w
             +  c.x *  c.x +  c.y *  c.y +  c.z *  c.z +  c.w *  c.w;
    #pragma unroll
    for (int m = 16; m; m >>= 1)
        ss += __shfl_xor_sync(0xffffffffu, ss, m);

    float inv_l2 = 1.0f / fmaxf(sqrtf(ss), 1e-12f);
    float nrm    = __ldg(norm + node);

    // h_out = h + c * norm
    float4 hv = ldcs4(reinterpret_cast<const float4*>(h) + node * 32 + lane);
    float4 ho;
    ho.x = hv.x + c.x * nrm;
    ho.y = hv.y + c.y * nrm;
    ho.z = hv.z + c.z * nrm;
    ho.w = hv.w + c.w * nrm;
    stcs4(reinterpret_cast<float4*>(out) + node * 32 + lane, ho);

    // b_out = concat(b, c) / l2
    float* bout = out + (size_t)NN * DD;
    float4 b1; b1.x = bv.x * inv_l2; b1.y = bv.y * inv_l2;
               b1.z = bv.z * inv_l2; b1.w = bv.w * inv_l2;
    float4 b2; b2.x =  c.x * inv_l2; b2.y =  c.y * inv_l2;
               b2.z =  c.z * inv_l2; b2.w =  c.w * inv_l2;
    stcs4(reinterpret_cast<float4*>(bout) + node * 64 + lane,      b1);
    stcs4(reinterpret_cast<float4*>(bout) + node * 64 + 32 + lane, b2);
}

// ---------------------------------------------------------------------------
extern "C" void kernel_launch(void* const* d_in, const int* in_sizes, int n_in,
                              void* d_out, int out_size)
{
    const float* h    = (const float*)d_in[0];
    const float* b    = (const float*)d_in[1];
    const float* norm = (const float*)d_in[2];
    const int*   esrc = (const int*)  d_in[3];
    const int*   edst = (const int*)  d_in[4];
    float*       out  = (float*)d_out;
    int E = in_sizes[3];
    if (E > EE) E = EE;

    void* zero_ptr = nullptr;
    cudaGetSymbolAddress(&zero_ptr, g_zero);
    cudaMemsetAsync(zero_ptr, 0, (size_t)NN * 4 + SCAN_NB * 8);

    // fused prescale ∥ hist
    int preB  = (NN * (DD / 4) + 255) / 256;            // 12500
    int histB = (E + 1023) / 1024;                      // 1563
    fused_pre_hist_kernel<<<preB + histB, 256>>>(h, norm, edst, E, preB);

    // single-pass scan -> rowstart + cursor
    scan_onepass_kernel<<<SCAN_NB, SCAN_TPB>>>(E);

    // CSR fill (8 edges per thread)
    int eb8 = (E / 8 + 255) / 256 + 1;
    fill_kernel<<<eb8, 256>>>(esrc, edst, E);

    // fused gather-mean + finalize: one warp per node
    long long threads = (long long)NN * 32;
    int blocks = (int)((threads + 255) / 256);
    gather_finalize_kernel<<<blocks, 256>>>(h, b, norm, out);
}